// round 1
// baseline (speedup 1.0000x reference)
#include <cuda_runtime.h>
#include <cstdint>

// Problem constants (fixed by setup_inputs): B=8, C=1, H=352, W=1216, K=3, times=24
#define Bn 8
#define Hn 352
#define Wn 1216
#define HW (Hn * Wn)            // 428032
#define BHW (Bn * HW)           // 3424256
#define NPLANES 8               // 8 non-center normalized weights (center = 1 - sum)
#define TIMES 24

// Scratch (static device globals — allocation-free per harness rules)
__device__ float    g_aff[(size_t)NPLANES * BHW];   // ~109.6 MB, fits (mostly) in 126 MB L2
__device__ float    g_feat0[BHW];
__device__ float    g_feat1[BHW];
__device__ unsigned g_mask[BHW / 32];               // 1 bit per pixel

// ---------------------------------------------------------------------------
// Prep: normalize |affinity| over the 9 taps, store the 8 non-center weights;
// build initial feature (sparse-depth clamped) and the validity bitmask.
// ---------------------------------------------------------------------------
__global__ void prep_kernel(const float* __restrict__ aff,
                            const float* __restrict__ feature,
                            const float* __restrict__ sparse)
{
    const int w  = blockIdx.x * 32 + threadIdx.x;   // W = 38*32, exact
    const int h  = blockIdx.y * 8  + threadIdx.y;   // H = 44*8,  exact
    const int b  = blockIdx.z;
    const int hw = h * Wn + w;
    const size_t idx = (size_t)b * HW + hw;

    const float* ap = aff + (size_t)b * 9 * HW + hw;
    float a[9];
    float s = 0.0f;
#pragma unroll
    for (int k = 0; k < 9; ++k) {
        a[k] = fabsf(__ldg(ap + (size_t)k * HW));
        s += a[k];
    }
    const float inv = 1.0f / s;

    int pk = 0;
#pragma unroll
    for (int k = 0; k < 9; ++k) {
        if (k == 4) continue;                      // center weight is implicit
        g_aff[(size_t)pk * BHW + idx] = a[k] * inv;
        ++pk;
    }

    const float sd = __ldg(sparse + idx);
    const bool  m  = sd > 0.0f;                    // sign(sparse_depth): sparse >= 0
    g_feat0[idx] = m ? sd : __ldg(feature + idx);

    const unsigned bal = __ballot_sync(0xFFFFFFFFu, m);
    if (threadIdx.x == 0) g_mask[idx >> 5] = bal;  // idx%32 == w%32 since W%32==0
}

// ---------------------------------------------------------------------------
// One propagation step: out = f_c + sum_{k!=4} w_k * (f_k - f_c),
// clamped back to the measurement at masked pixels (where f_c == sparse).
// ---------------------------------------------------------------------------
__global__ void step_kernel(const float* __restrict__ fin,
                            float* __restrict__ fout)
{
    const int w  = blockIdx.x * 32 + threadIdx.x;
    const int h  = blockIdx.y * 8  + threadIdx.y;
    const int b  = blockIdx.z;
    const int hw = h * Wn + w;
    const size_t idx = (size_t)b * HW + hw;
    const float* fb  = fin + (size_t)b * HW;

    const bool hm = (h > 0), hp = (h < Hn - 1);
    const bool wm = (w > 0), wp = (w < Wn - 1);

    const float fc = __ldg(fb + hw);
    const float f0 = (hm && wm) ? __ldg(fb + hw - Wn - 1) : 0.0f;
    const float f1 =  hm        ? __ldg(fb + hw - Wn    ) : 0.0f;
    const float f2 = (hm && wp) ? __ldg(fb + hw - Wn + 1) : 0.0f;
    const float f3 =  wm        ? __ldg(fb + hw      - 1) : 0.0f;
    const float f5 =  wp        ? __ldg(fb + hw      + 1) : 0.0f;
    const float f6 = (hp && wm) ? __ldg(fb + hw + Wn - 1) : 0.0f;
    const float f7 =  hp        ? __ldg(fb + hw + Wn    ) : 0.0f;
    const float f8 = (hp && wp) ? __ldg(fb + hw + Wn + 1) : 0.0f;

    const float* A = g_aff + idx;
    float out = fc;
    out = fmaf(__ldg(A + 0 * (size_t)BHW), f0 - fc, out);
    out = fmaf(__ldg(A + 1 * (size_t)BHW), f1 - fc, out);
    out = fmaf(__ldg(A + 2 * (size_t)BHW), f2 - fc, out);
    out = fmaf(__ldg(A + 3 * (size_t)BHW), f3 - fc, out);
    out = fmaf(__ldg(A + 4 * (size_t)BHW), f5 - fc, out);
    out = fmaf(__ldg(A + 5 * (size_t)BHW), f6 - fc, out);
    out = fmaf(__ldg(A + 6 * (size_t)BHW), f7 - fc, out);
    out = fmaf(__ldg(A + 7 * (size_t)BHW), f8 - fc, out);

    const unsigned mword = __ldg(&g_mask[idx >> 5]);   // 1 load per warp (broadcast)
    const bool m = (mword >> (w & 31)) & 1u;
    fout[idx] = m ? fc : out;
}

// ---------------------------------------------------------------------------
// Launch: prep + 24 ping-pong steps, final step writes d_out.
// 'times' (d_in[3]) is fixed at 24 by the problem; device scalars cannot be
// read host-side under graph capture, so the loop count is compiled in.
// ---------------------------------------------------------------------------
extern "C" void kernel_launch(void* const* d_in, const int* in_sizes, int n_in,
                              void* d_out, int out_size)
{
    const float* aff     = (const float*)d_in[0];
    const float* feature = (const float*)d_in[1];
    const float* sparse  = (const float*)d_in[2];
    float* out = (float*)d_out;

    float* f0 = nullptr;
    float* f1 = nullptr;
    cudaGetSymbolAddress((void**)&f0, g_feat0);
    cudaGetSymbolAddress((void**)&f1, g_feat1);

    const dim3 blk(32, 8);
    const dim3 grd(Wn / 32, Hn / 8, Bn);

    prep_kernel<<<grd, blk>>>(aff, feature, sparse);

    for (int t = 0; t < TIMES; ++t) {
        const float* fin  = (t & 1) ? f1 : f0;
        float*       fout = (t == TIMES - 1) ? out : ((t & 1) ? f0 : f1);
        step_kernel<<<grd, blk>>>(fin, fout);
    }
}

// round 3
// speedup vs baseline: 2.0358x; 2.0358x over previous
#include <cuda_runtime.h>
#include <cuda_fp16.h>
#include <cstdint>

// Problem constants (fixed by setup_inputs): B=8, C=1, H=352, W=1216, times=24
#define Bn 8
#define Hn 352
#define Wn 1216
#define HW (Hn * Wn)            // 428032
#define BHW (Bn * HW)           // 3424256
#define TIMES 24

// Padded feature layout: stride 1248 (multiple of 32 floats), interior at
// column offset 16, one guard row top/bottom. Guard cells are ALWAYS zero,
// so out-of-image taps read genuine zeros (matching reference zero-padding).
#define PSTR 1248
#define PIMG ((Hn + 2) * PSTR)  // 441792 floats per image
#define COFF 16                 // interior column offset

// Static device scratch (allocation-free). Working set:
//   aff fp16 packed: 54.8 MB + feat 2x14.1 MB + mask 0.43 MB = ~84 MB < 126 MB L2
__device__ uint4    g_affp[BHW];                    // 8 fp16 weights per pixel
__device__ float    g_feat0[(size_t)Bn * PIMG];
__device__ float    g_feat1[(size_t)Bn * PIMG];
__device__ unsigned g_mask[BHW / 32];

// ---------------------------------------------------------------------------
// Zero the guard cells of both padded feature buffers (top/bottom rows +
// left/right guard columns). Interior is written by prep/step.
// ---------------------------------------------------------------------------
__global__ void guard_zero_kernel()
{
    const int i = blockIdx.x * 256 + threadIdx.x;
    const int nTB = Bn * 2 * PSTR;                    // top+bottom full rows
    if (i < nTB) {
        const int img = i / (2 * PSTR);
        const int r   = (i / PSTR) & 1;               // 0=top, 1=bottom
        const int c   = i % PSTR;
        const size_t off = (size_t)img * PIMG + (size_t)(r ? (Hn + 1) : 0) * PSTR + c;
        g_feat0[off] = 0.0f;
        g_feat1[off] = 0.0f;
    }
    const int j = i - nTB;
    if (j >= 0 && j < Bn * Hn * 32) {                 // 16 left + 16 right guard cols
        const int img = j / (Hn * 32);
        const int rem = j % (Hn * 32);
        const int r   = rem / 32;
        const int c   = rem % 32;
        const int col = (c < 16) ? c : (COFF + Wn + (c - 16));
        const size_t off = (size_t)img * PIMG + (size_t)(r + 1) * PSTR + col;
        g_feat0[off] = 0.0f;
        g_feat1[off] = 0.0f;
    }
}

// ---------------------------------------------------------------------------
// Prep: normalize |affinity|, pack the 8 non-center weights as fp16 into one
// uint4 per pixel; build initial padded feature and the validity bitmask.
// ---------------------------------------------------------------------------
__global__ void prep_kernel(const float* __restrict__ aff,
                            const float* __restrict__ feature,
                            const float* __restrict__ sparse)
{
    const int w  = blockIdx.x * 32 + threadIdx.x;   // W = 38*32 exact
    const int h  = blockIdx.y * 8  + threadIdx.y;   // H = 44*8 exact
    const int b  = blockIdx.z;
    const int hw = h * Wn + w;
    const size_t idx = (size_t)b * HW + hw;

    const float* ap = aff + (size_t)b * 9 * HW + hw;
    float a[9];
    float s = 0.0f;
#pragma unroll
    for (int k = 0; k < 9; ++k) {
        a[k] = fabsf(__ldg(ap + (size_t)k * HW));
        s += a[k];
    }
    const float inv = 1.0f / s;

    // taps in step order: (-1,-1)(-1,0)(-1,+1)(0,-1)(0,+1)(+1,-1)(+1,0)(+1,+1)
    __half2 h01 = __floats2half2_rn(a[0] * inv, a[1] * inv);
    __half2 h23 = __floats2half2_rn(a[2] * inv, a[3] * inv);
    __half2 h56 = __floats2half2_rn(a[5] * inv, a[6] * inv);
    __half2 h78 = __floats2half2_rn(a[7] * inv, a[8] * inv);
    uint4 wv;
    wv.x = *reinterpret_cast<unsigned*>(&h01);
    wv.y = *reinterpret_cast<unsigned*>(&h23);
    wv.z = *reinterpret_cast<unsigned*>(&h56);
    wv.w = *reinterpret_cast<unsigned*>(&h78);
    g_affp[idx] = wv;

    const float sd = __ldg(sparse + idx);
    const bool  m  = sd > 0.0f;
    const size_t pidx = (size_t)b * PIMG + (size_t)(h + 1) * PSTR + (w + COFF);
    g_feat0[pidx] = m ? sd : __ldg(feature + idx);

    const unsigned bal = __ballot_sync(0xFFFFFFFFu, m);
    if (threadIdx.x == 0) g_mask[idx >> 5] = bal;
}

// ---------------------------------------------------------------------------
// One propagation step on the padded layout. All 9 taps unconditional
// (guards are zero). Output addressing parameterized so the last step can
// write the unpadded d_out directly.
// ---------------------------------------------------------------------------
__global__ void step_kernel(const float* __restrict__ fin,
                            float* __restrict__ fout,
                            int oImg, int oStr, int oOff)
{
    const int w  = blockIdx.x * 32 + threadIdx.x;
    const int h  = blockIdx.y * 8  + threadIdx.y;
    const int b  = blockIdx.z;
    const size_t idx  = (size_t)b * HW + h * Wn + w;
    const size_t pidx = (size_t)b * PIMG + (size_t)(h + 1) * PSTR + (w + COFF);

    const float fc = __ldg(fin + pidx);
    const float f0 = __ldg(fin + pidx - PSTR - 1);
    const float f1 = __ldg(fin + pidx - PSTR);
    const float f2 = __ldg(fin + pidx - PSTR + 1);
    const float f3 = __ldg(fin + pidx - 1);
    const float f5 = __ldg(fin + pidx + 1);
    const float f6 = __ldg(fin + pidx + PSTR - 1);
    const float f7 = __ldg(fin + pidx + PSTR);
    const float f8 = __ldg(fin + pidx + PSTR + 1);

    const uint4 wv = __ldg(&g_affp[idx]);
    const __half2* hp = reinterpret_cast<const __half2*>(&wv);
    const float2 p0 = __half22float2(hp[0]);
    const float2 p1 = __half22float2(hp[1]);
    const float2 p2 = __half22float2(hp[2]);
    const float2 p3 = __half22float2(hp[3]);

    float out = fc;
    out = fmaf(p0.x, f0 - fc, out);
    out = fmaf(p0.y, f1 - fc, out);
    out = fmaf(p1.x, f2 - fc, out);
    out = fmaf(p1.y, f3 - fc, out);
    out = fmaf(p2.x, f5 - fc, out);
    out = fmaf(p2.y, f6 - fc, out);
    out = fmaf(p3.x, f7 - fc, out);
    out = fmaf(p3.y, f8 - fc, out);

    const unsigned mword = __ldg(&g_mask[idx >> 5]);
    const bool m = (mword >> (w & 31)) & 1u;

    const size_t oidx = (size_t)b * oImg + (size_t)h * oStr + w + oOff;
    fout[oidx] = m ? fc : out;
}

// ---------------------------------------------------------------------------
extern "C" void kernel_launch(void* const* d_in, const int* in_sizes, int n_in,
                              void* d_out, int out_size)
{
    const float* aff     = (const float*)d_in[0];
    const float* feature = (const float*)d_in[1];
    const float* sparse  = (const float*)d_in[2];
    float* out = (float*)d_out;

    float* f0 = nullptr;
    float* f1 = nullptr;
    cudaGetSymbolAddress((void**)&f0, g_feat0);
    cudaGetSymbolAddress((void**)&f1, g_feat1);

    const dim3 blk(32, 8);
    const dim3 grd(Wn / 32, Hn / 8, Bn);

    guard_zero_kernel<<<512, 256>>>();
    prep_kernel<<<grd, blk>>>(aff, feature, sparse);

    for (int t = 0; t < TIMES; ++t) {
        const float* fin = (t & 1) ? f1 : f0;
        if (t == TIMES - 1) {
            step_kernel<<<grd, blk>>>(fin, out, HW, Wn, 0);
        } else {
            float* fout = (t & 1) ? f0 : f1;
            step_kernel<<<grd, blk>>>(fin, fout, PIMG, PSTR, PSTR + COFF);
        }
    }
}